// round 1
// baseline (speedup 1.0000x reference)
#include <cuda_runtime.h>

#define X_CH   256
#define Y_CH   512
#define DIM    128
#define NHEAD  4
#define HD     32
#define HWX    4096
#define HWY    1024
#define BATCH  2
#define GAMMA  0.17677669529663687f   // 32^-0.5

// ---------------- scratch (device globals; no allocation) ----------------
static __device__ float g_qx[BATCH*NHEAD*HWX*HD];
static __device__ float g_kx[BATCH*NHEAD*HWX*HD];
static __device__ float g_vx[BATCH*NHEAD*HWX*HD];
static __device__ float g_qy[BATCH*NHEAD*HWY*HD];
static __device__ float g_ky[BATCH*NHEAD*HWY*HD];
static __device__ float g_vy[BATCH*NHEAD*HWY*HD];
static __device__ float g_ax[BATCH*NHEAD*HWX*HD];   // attention out, [b,h,p,d]
static __device__ float g_ay[BATCH*NHEAD*HWY*HD];

// ================= QKV GEMM: C[384,N] = W[384,K] * X[K,N] + bias ==========
// Epilogue scatters into q/k/v with layout [B,H,HW,D] (d contiguous).
__global__ void __launch_bounds__(256) gemm_qkv_kernel(
    const float* __restrict__ W, const float* __restrict__ X,
    const float* __restrict__ bias, int which, int KDIM, int N)
{
    float *Qo, *Ko, *Vo;
    if (which == 0) { Qo = g_qx; Ko = g_kx; Vo = g_vx; }
    else            { Qo = g_qy; Ko = g_ky; Vo = g_vy; }

    __shared__ __align__(16) float As[16][64];
    __shared__ __align__(16) float Bs[16][64];

    const int b  = blockIdx.z;
    const int m0 = blockIdx.y * 64, n0 = blockIdx.x * 64;
    const float* Xb = X + (size_t)b * KDIM * N;
    const int tid = threadIdx.x;
    const int ty = tid >> 4, tx = tid & 15;
    const int am = tid >> 2, ak = (tid & 3) << 2;     // A tile: 64 rows x 16 k
    const int bk = tid >> 4, bn = (tid & 15) << 2;    // B tile: 16 k x 64 n

    float acc[4][4] = {};

    for (int k0 = 0; k0 < KDIM; k0 += 16) {
        float4 av = *(const float4*)(W  + (size_t)(m0 + am) * KDIM + k0 + ak);
        float4 bv = *(const float4*)(Xb + (size_t)(k0 + bk) * N + n0 + bn);
        As[ak+0][am] = av.x; As[ak+1][am] = av.y; As[ak+2][am] = av.z; As[ak+3][am] = av.w;
        *(float4*)(&Bs[bk][bn]) = bv;
        __syncthreads();
        #pragma unroll
        for (int kk = 0; kk < 16; kk++) {
            float4 a4 = *(const float4*)(&As[kk][ty << 2]);
            float4 b4 = *(const float4*)(&Bs[kk][tx << 2]);
            float ar[4] = {a4.x, a4.y, a4.z, a4.w};
            float br[4] = {b4.x, b4.y, b4.z, b4.w};
            #pragma unroll
            for (int i = 0; i < 4; i++)
                #pragma unroll
                for (int j = 0; j < 4; j++)
                    acc[i][j] += ar[i] * br[j];
        }
        __syncthreads();
    }

    #pragma unroll
    for (int i = 0; i < 4; i++) {
        int o = m0 + (ty << 2) + i;          // channel in [0,384)
        float bval = bias[o];
        int t = o >> 7, r = o & 127, h = r >> 5, d = r & 31;
        float* base = (t == 0) ? Qo : ((t == 1) ? Ko : Vo);
        size_t rb = (size_t)(b * NHEAD + h) * N;
        #pragma unroll
        for (int j = 0; j < 4; j++) {
            int n = n0 + (tx << 2) + j;
            base[(rb + n) * HD + d] = acc[i][j] + bval;
        }
    }
}

// ========== Proj GEMM: Out[b,OC,N] = W[OC,128]*Att + bias + Res ===========
// Att stored as [B,H,N,D] (k = h*32+d contiguous per pixel).
__global__ void __launch_bounds__(256) gemm_proj_kernel(
    const float* __restrict__ W, const float* __restrict__ bias,
    const float* __restrict__ Res, float* __restrict__ Out,
    int which, int OC, int N)
{
    const float* Att = which ? g_ay : g_ax;

    __shared__ __align__(16) float As[16][64];
    __shared__ __align__(16) float Bs[16][64];

    const int b  = blockIdx.z;
    const int m0 = blockIdx.y * 64, n0 = blockIdx.x * 64;
    const int tid = threadIdx.x;
    const int ty = tid >> 4, tx = tid & 15;
    const int am = tid >> 2, ak = (tid & 3) << 2;
    const int bn_ = tid >> 2, bkq = (tid & 3) << 2;   // read 4 k per thread (transpose)

    float acc[4][4] = {};

    for (int k0 = 0; k0 < DIM; k0 += 16) {
        float4 av = *(const float4*)(W + (size_t)(m0 + am) * DIM + k0 + ak);
        int c = k0 + bkq;                 // 4 consecutive channels stay in one head
        int h = c >> 5, d = c & 31;
        float4 bv = *(const float4*)(Att + ((size_t)(b * NHEAD + h) * N + n0 + bn_) * HD + d);
        As[ak+0][am] = av.x; As[ak+1][am] = av.y; As[ak+2][am] = av.z; As[ak+3][am] = av.w;
        Bs[bkq+0][bn_] = bv.x; Bs[bkq+1][bn_] = bv.y; Bs[bkq+2][bn_] = bv.z; Bs[bkq+3][bn_] = bv.w;
        __syncthreads();
        #pragma unroll
        for (int kk = 0; kk < 16; kk++) {
            float4 a4 = *(const float4*)(&As[kk][ty << 2]);
            float4 b4 = *(const float4*)(&Bs[kk][tx << 2]);
            float ar[4] = {a4.x, a4.y, a4.z, a4.w};
            float br[4] = {b4.x, b4.y, b4.z, b4.w};
            #pragma unroll
            for (int i = 0; i < 4; i++)
                #pragma unroll
                for (int j = 0; j < 4; j++)
                    acc[i][j] += ar[i] * br[j];
        }
        __syncthreads();
    }

    #pragma unroll
    for (int i = 0; i < 4; i++) {
        int o = m0 + (ty << 2) + i;
        float bval = bias[o];
        size_t off = ((size_t)b * OC + o) * N + n0 + (tx << 2);
        float4 r = *(const float4*)(Res + off);
        float4 v;
        v.x = acc[i][0] + bval + r.x;
        v.y = acc[i][1] + bval + r.y;
        v.z = acc[i][2] + bval + r.z;
        v.w = acc[i][3] + bval + r.w;
        *(float4*)(Out + off) = v;
    }
}

// ================= Flash attention: O = softmax(Q K^T * g) V ==============
// grid: (NQ/32, B*H). 8 warps/block, 4 queries/warp, online softmax.
// lane = key index for scores, lane = dim index for accumulation.
__global__ void __launch_bounds__(256) attn_kernel(int dir, int NQ, int NK)
{
    const float *Q, *K, *V; float* O;
    if (dir == 0) { Q = g_qx; K = g_ky; V = g_vy; O = g_ax; }
    else          { Q = g_qy; K = g_kx; V = g_vx; O = g_ay; }

    __shared__ float Ks[32 * 33];
    __shared__ float Vs[32 * 33];
    __shared__ __align__(16) float Qs[32 * 32];

    const int bh = blockIdx.y;
    const size_t qb = (size_t)bh * NQ * HD;
    const size_t kb = (size_t)bh * NK * HD;
    const int tid = threadIdx.x, w = tid >> 5, lane = tid & 31;
    const int q0 = blockIdx.x * 32;

    for (int e = tid; e < 32 * 32; e += 256)
        Qs[e] = Q[qb + (size_t)q0 * HD + e] * GAMMA;

    float m[4], l[4], acc[4];
    #pragma unroll
    for (int i = 0; i < 4; i++) { m[i] = -1e30f; l[i] = 0.f; acc[i] = 0.f; }

    const int rr = tid >> 3, cc = (tid & 7) << 2;     // coop K/V tile load
    const float* Kp = K + kb + (size_t)rr * HD + cc;
    const float* Vp = V + kb + (size_t)rr * HD + cc;
    const int nt = NK >> 5;

    for (int t = 0; t < nt; t++) {
        __syncthreads();
        float4 kv = *(const float4*)(Kp + (size_t)t * 32 * HD);
        float4 vv = *(const float4*)(Vp + (size_t)t * 32 * HD);
        float* kd = &Ks[rr * 33 + cc]; kd[0]=kv.x; kd[1]=kv.y; kd[2]=kv.z; kd[3]=kv.w;
        float* vd = &Vs[rr * 33 + cc]; vd[0]=vv.x; vd[1]=vv.y; vd[2]=vv.z; vd[3]=vv.w;
        __syncthreads();

        // scores: lane handles key (t*32 + lane) for 4 queries
        float s[4] = {0.f, 0.f, 0.f, 0.f};
        const float* krow = &Ks[lane * 33];
        #pragma unroll
        for (int d4 = 0; d4 < 8; d4++) {
            float k0v = krow[d4*4+0], k1v = krow[d4*4+1];
            float k2v = krow[d4*4+2], k3v = krow[d4*4+3];
            #pragma unroll
            for (int i = 0; i < 4; i++) {
                float4 qv = *(const float4*)(&Qs[((w << 2) + i) * HD + (d4 << 2)]);
                s[i] += qv.x*k0v + qv.y*k1v + qv.z*k2v + qv.w*k3v;
            }
        }

        // online softmax update
        float p[4];
        #pragma unroll
        for (int i = 0; i < 4; i++) {
            float tmax = s[i];
            #pragma unroll
            for (int o = 16; o > 0; o >>= 1)
                tmax = fmaxf(tmax, __shfl_xor_sync(0xffffffffu, tmax, o));
            float mn = fmaxf(m[i], tmax);
            float corr = __expf(m[i] - mn);
            p[i] = __expf(s[i] - mn);
            float ps = p[i];
            #pragma unroll
            for (int o = 16; o > 0; o >>= 1)
                ps += __shfl_xor_sync(0xffffffffu, ps, o);
            l[i] = l[i] * corr + ps;
            acc[i] *= corr;
            m[i] = mn;
        }

        // AV: lane now = output dim
        #pragma unroll
        for (int j = 0; j < 32; j++) {
            float vvj = Vs[j * 33 + lane];
            #pragma unroll
            for (int i = 0; i < 4; i++)
                acc[i] += __shfl_sync(0xffffffffu, p[i], j) * vvj;
        }
    }

    #pragma unroll
    for (int i = 0; i < 4; i++)
        O[qb + (size_t)(q0 + (w << 2) + i) * HD + lane] = acc[i] / l[i];
}

// ============================== launcher ==================================
extern "C" void kernel_launch(void* const* d_in, const int* in_sizes, int n_in,
                              void* d_out, int out_size)
{
    (void)out_size;
    const float *x=0, *y=0, *wxq=0, *bxq=0, *wyq=0, *byq=0,
                *wpx=0, *bpx=0, *wpy=0, *bpy=0;
    for (int i = 0; i < n_in; i++) {
        const float* p = (const float*)d_in[i];
        switch (in_sizes[i]) {
            case 2097152: x = p;   break;   // [2,256,64,64]
            case 1048576: y = p;   break;   // [2,512,32,32]
            case 98304:   wxq = p; break;   // [384,256]
            case 196608:  wyq = p; break;   // [384,512]
            case 32768:   wpx = p; break;   // [256,128]
            case 65536:   wpy = p; break;   // [512,128]
            case 256:     bpx = p; break;
            case 512:     bpy = p; break;
            case 384:     if (!bxq) bxq = p; else byq = p; break;
            default: break;
        }
    }
    float* out = (float*)d_out;
    dim3 blk(256);

    gemm_qkv_kernel<<<dim3(HWX/64, 384/64, BATCH), blk>>>(wxq, x, bxq, 0, X_CH, HWX);
    gemm_qkv_kernel<<<dim3(HWY/64, 384/64, BATCH), blk>>>(wyq, y, byq, 1, Y_CH, HWY);

    attn_kernel<<<dim3(HWX/32, BATCH*NHEAD), blk>>>(0, HWX, HWY);   // x attends y
    attn_kernel<<<dim3(HWY/32, BATCH*NHEAD), blk>>>(1, HWY, HWX);   // y attends x

    gemm_proj_kernel<<<dim3(HWX/64, X_CH/64, BATCH), blk>>>(wpx, bpx, x, out, 0, X_CH, HWX);
    gemm_proj_kernel<<<dim3(HWY/64, Y_CH/64, BATCH), blk>>>(
        wpy, bpy, y, out + (size_t)BATCH*X_CH*HWX, 1, Y_CH, HWY);
}

// round 2
// speedup vs baseline: 2.6984x; 2.6984x over previous
#include <cuda_runtime.h>
#include <cuda_bf16.h>

#define X_CH   256
#define Y_CH   512
#define DIM    128
#define NHEAD  4
#define HD     32
#define HWX    4096
#define HWY    1024
#define BATCH  2
#define GAMMA  0.17677669529663687f   // 32^-0.5

typedef __nv_bfloat16 bf16;

// ---------------- scratch (device globals; no allocation) ----------------
// split-bf16 Q/K ([b,h,n,d]) and V transposed ([b,h,d,n])
static __device__ bf16 g_qxh[BATCH*NHEAD*HWX*HD], g_qxl[BATCH*NHEAD*HWX*HD];
static __device__ bf16 g_kxh[BATCH*NHEAD*HWX*HD], g_kxl[BATCH*NHEAD*HWX*HD];
static __device__ bf16 g_vxh[BATCH*NHEAD*HWX*HD], g_vxl[BATCH*NHEAD*HWX*HD];
static __device__ bf16 g_qyh[BATCH*NHEAD*HWY*HD], g_qyl[BATCH*NHEAD*HWY*HD];
static __device__ bf16 g_kyh[BATCH*NHEAD*HWY*HD], g_kyl[BATCH*NHEAD*HWY*HD];
static __device__ bf16 g_vyh[BATCH*NHEAD*HWY*HD], g_vyl[BATCH*NHEAD*HWY*HD];
static __device__ float g_ax[BATCH*NHEAD*HWX*HD];   // attention out, [b,h,p,d]
static __device__ float g_ay[BATCH*NHEAD*HWY*HD];

__device__ __forceinline__ void bsplit(float v, bf16& h, bf16& l) {
    h = __float2bfloat16(v);
    l = __float2bfloat16(v - __bfloat162float(h));
}

// ================= QKV GEMM: C[384,N] = W[384,K] * X[K,N] + bias ==========
// Epilogue scatters split-bf16 into q (scaled by GAMMA), k [b,h,n,d], v^T [b,h,d,n].
__global__ void __launch_bounds__(256) gemm_qkv_kernel(
    const float* __restrict__ W, const float* __restrict__ X,
    const float* __restrict__ bias, int which, int KDIM, int N)
{
    bf16 *Qh, *Ql, *Kh, *Kl, *Vh, *Vl;
    if (which == 0) { Qh=g_qxh; Ql=g_qxl; Kh=g_kxh; Kl=g_kxl; Vh=g_vxh; Vl=g_vxl; }
    else            { Qh=g_qyh; Ql=g_qyl; Kh=g_kyh; Kl=g_kyl; Vh=g_vyh; Vl=g_vyl; }

    __shared__ __align__(16) float As[16][64];
    __shared__ __align__(16) float Bs[16][64];

    const int b  = blockIdx.z;
    const int m0 = blockIdx.y * 64, n0 = blockIdx.x * 64;
    const float* Xb = X + (size_t)b * KDIM * N;
    const int tid = threadIdx.x;
    const int ty = tid >> 4, tx = tid & 15;
    const int am = tid >> 2, ak = (tid & 3) << 2;
    const int bk = tid >> 4, bn = (tid & 15) << 2;

    float acc[4][4] = {};

    for (int k0 = 0; k0 < KDIM; k0 += 16) {
        float4 av = *(const float4*)(W  + (size_t)(m0 + am) * KDIM + k0 + ak);
        float4 bv = *(const float4*)(Xb + (size_t)(k0 + bk) * N + n0 + bn);
        As[ak+0][am] = av.x; As[ak+1][am] = av.y; As[ak+2][am] = av.z; As[ak+3][am] = av.w;
        *(float4*)(&Bs[bk][bn]) = bv;
        __syncthreads();
        #pragma unroll
        for (int kk = 0; kk < 16; kk++) {
            float4 a4 = *(const float4*)(&As[kk][ty << 2]);
            float4 b4 = *(const float4*)(&Bs[kk][tx << 2]);
            float ar[4] = {a4.x, a4.y, a4.z, a4.w};
            float br[4] = {b4.x, b4.y, b4.z, b4.w};
            #pragma unroll
            for (int i = 0; i < 4; i++)
                #pragma unroll
                for (int j = 0; j < 4; j++)
                    acc[i][j] += ar[i] * br[j];
        }
        __syncthreads();
    }

    #pragma unroll
    for (int i = 0; i < 4; i++) {
        int o = m0 + (ty << 2) + i;          // channel in [0,384)
        float bval = bias[o];
        int t = o >> 7, r = o & 127, h = r >> 5, d = r & 31;
        size_t rb = (size_t)(b * NHEAD + h) * N;
        #pragma unroll
        for (int j = 0; j < 4; j++) {
            int n = n0 + (tx << 2) + j;
            float v = acc[i][j] + bval;
            bf16 hh, ll;
            if (t == 0) {
                bsplit(v * GAMMA, hh, ll);
                Qh[(rb + n) * HD + d] = hh;  Ql[(rb + n) * HD + d] = ll;
            } else if (t == 1) {
                bsplit(v, hh, ll);
                Kh[(rb + n) * HD + d] = hh;  Kl[(rb + n) * HD + d] = ll;
            } else {
                size_t vi = ((size_t)(b * NHEAD + h) * HD + d) * N + n;
                bsplit(v, hh, ll);
                Vh[vi] = hh;  Vl[vi] = ll;
            }
        }
    }
}

// ========== Proj GEMM: Out[b,OC,N] = W[OC,128]*Att + bias + Res ===========
__global__ void __launch_bounds__(256) gemm_proj_kernel(
    const float* __restrict__ W, const float* __restrict__ bias,
    const float* __restrict__ Res, float* __restrict__ Out,
    int which, int OC, int N)
{
    const float* Att = which ? g_ay : g_ax;

    __shared__ __align__(16) float As[16][64];
    __shared__ __align__(16) float Bs[16][64];

    const int b  = blockIdx.z;
    const int m0 = blockIdx.y * 64, n0 = blockIdx.x * 64;
    const int tid = threadIdx.x;
    const int ty = tid >> 4, tx = tid & 15;
    const int am = tid >> 2, ak = (tid & 3) << 2;
    const int bn_ = tid >> 2, bkq = (tid & 3) << 2;

    float acc[4][4] = {};

    for (int k0 = 0; k0 < DIM; k0 += 16) {
        float4 av = *(const float4*)(W + (size_t)(m0 + am) * DIM + k0 + ak);
        int c = k0 + bkq;
        int h = c >> 5, d = c & 31;
        float4 bv = *(const float4*)(Att + ((size_t)(b * NHEAD + h) * N + n0 + bn_) * HD + d);
        As[ak+0][am] = av.x; As[ak+1][am] = av.y; As[ak+2][am] = av.z; As[ak+3][am] = av.w;
        Bs[bkq+0][bn_] = bv.x; Bs[bkq+1][bn_] = bv.y; Bs[bkq+2][bn_] = bv.z; Bs[bkq+3][bn_] = bv.w;
        __syncthreads();
        #pragma unroll
        for (int kk = 0; kk < 16; kk++) {
            float4 a4 = *(const float4*)(&As[kk][ty << 2]);
            float4 b4 = *(const float4*)(&Bs[kk][tx << 2]);
            float ar[4] = {a4.x, a4.y, a4.z, a4.w};
            float br[4] = {b4.x, b4.y, b4.z, b4.w};
            #pragma unroll
            for (int i = 0; i < 4; i++)
                #pragma unroll
                for (int j = 0; j < 4; j++)
                    acc[i][j] += ar[i] * br[j];
        }
        __syncthreads();
    }

    #pragma unroll
    for (int i = 0; i < 4; i++) {
        int o = m0 + (ty << 2) + i;
        float bval = bias[o];
        size_t off = ((size_t)b * OC + o) * N + n0 + (tx << 2);
        float4 r = *(const float4*)(Res + off);
        float4 v;
        v.x = acc[i][0] + bval + r.x;
        v.y = acc[i][1] + bval + r.y;
        v.z = acc[i][2] + bval + r.z;
        v.w = acc[i][3] + bval + r.w;
        *(float4*)(Out + off) = v;
    }
}

// ================= MMA flash attention (bf16x3 split) ======================
__device__ __forceinline__ void ldsm4(unsigned r[4], const void* p) {
    unsigned a = (unsigned)__cvta_generic_to_shared(p);
    asm volatile("ldmatrix.sync.aligned.m8n8.x4.shared.b16 {%0,%1,%2,%3}, [%4];"
        : "=r"(r[0]), "=r"(r[1]), "=r"(r[2]), "=r"(r[3]) : "r"(a));
}
__device__ __forceinline__ void mma16816(float c[4], const unsigned a[4],
                                         unsigned b0, unsigned b1) {
    asm volatile("mma.sync.aligned.m16n8k16.row.col.f32.bf16.bf16.f32 "
        "{%0,%1,%2,%3}, {%4,%5,%6,%7}, {%8,%9}, {%0,%1,%2,%3};"
        : "+f"(c[0]), "+f"(c[1]), "+f"(c[2]), "+f"(c[3])
        : "r"(a[0]), "r"(a[1]), "r"(a[2]), "r"(a[3]), "r"(b0), "r"(b1));
}
__device__ __forceinline__ unsigned pack2(bf16 a, bf16 b) {
    return (unsigned)__bfloat16_as_ushort(a) | ((unsigned)__bfloat16_as_ushort(b) << 16);
}

#define QSTR 40   // smem row stride for [n][32d] tiles (conflict-free ldmatrix)
#define VSTR 72   // smem row stride for [d][64key] tiles

// 64 queries/block, 4 warps (16 q each), KV tile 64 keys.
// blocks [0,128): y attends x (long blocks first); [128,640): x attends y.
__global__ void __launch_bounds__(128) attn_mma_kernel()
{
    __shared__ bf16 Qs[2][64 * QSTR];
    __shared__ bf16 Ks[2][64 * QSTR];
    __shared__ bf16 Vs[2][32 * VSTR];

    int blk = blockIdx.x;
    const bf16 *Qh, *Ql, *Kh, *Kl, *Vh, *Vl; float* O;
    int NQ, NK, bh, q0;
    if (blk < 128) {   // dir1: y attends x
        bh = blk >> 4; q0 = (blk & 15) * 64; NQ = HWY; NK = HWX;
        Qh=g_qyh; Ql=g_qyl; Kh=g_kxh; Kl=g_kxl; Vh=g_vxh; Vl=g_vxl; O=g_ay;
    } else {           // dir0: x attends y
        blk -= 128;
        bh = blk >> 6; q0 = (blk & 63) * 64; NQ = HWX; NK = HWY;
        Qh=g_qxh; Ql=g_qxl; Kh=g_kyh; Kl=g_kyl; Vh=g_vyh; Vl=g_vyl; O=g_ax;
    }

    const int tid = threadIdx.x, w = tid >> 5, lane = tid & 31;

    // load Q tile (64x32, hi+lo)
    {
        const size_t base = (size_t)bh * NQ * HD + (size_t)q0 * HD;
        #pragma unroll
        for (int part = 0; part < 2; part++) {
            const bf16* src = (part ? Ql : Qh) + base;
            #pragma unroll
            for (int it = 0; it < 2; it++) {
                int e = (tid + it * 128) * 8;
                int row = e >> 5, col = e & 31;
                *(uint4*)&Qs[part][row * QSTR + col] = *(const uint4*)(src + row * HD + col);
            }
        }
    }
    __syncthreads();

    // Q fragments: [part][kchunk][4]
    const int arow = (lane & 7) + ((lane & 8) ? 8 : 0);
    const int acol = (lane & 16) ? 8 : 0;
    const int brow = (lane & 7) + ((lane & 16) ? 8 : 0);
    const int bcol = (lane & 8) ? 8 : 0;
    unsigned qf[2][2][4];
    #pragma unroll
    for (int p = 0; p < 2; p++)
        #pragma unroll
        for (int c = 0; c < 2; c++)
            ldsm4(qf[p][c], &Qs[p][(w * 16 + arow) * QSTR + c * 16 + acol]);

    float m0r = -1e30f, m1r = -1e30f, l0 = 0.f, l1 = 0.f;
    float oacc[4][4] = {};

    const int nt = NK >> 6;
    const size_t kbase = (size_t)bh * NK * HD;
    const size_t vbase = (size_t)bh * HD * NK;

    for (int kt = 0; kt < nt; kt++) {
        __syncthreads();
        {   // cooperative K (64x32) + V^T (32x64) tile load, hi+lo
            #pragma unroll
            for (int it = 0; it < 2; it++) {
                int e = (tid + it * 128) * 8;
                int krow = e >> 5, kcol = e & 31;
                int vrow = e >> 6, vcol = e & 63;
                size_t kg = kbase + (size_t)(kt * 64 + krow) * HD + kcol;
                size_t vg = vbase + (size_t)vrow * NK + kt * 64 + vcol;
                *(uint4*)&Ks[0][krow * QSTR + kcol] = *(const uint4*)(Kh + kg);
                *(uint4*)&Ks[1][krow * QSTR + kcol] = *(const uint4*)(Kl + kg);
                *(uint4*)&Vs[0][vrow * VSTR + vcol] = *(const uint4*)(Vh + vg);
                *(uint4*)&Vs[1][vrow * VSTR + vcol] = *(const uint4*)(Vl + vg);
            }
        }
        __syncthreads();

        // S = Q K^T  (16q x 64keys per warp), bf16x3
        float s[8][4];
        #pragma unroll
        for (int nb = 0; nb < 8; nb++)
            s[nb][0] = s[nb][1] = s[nb][2] = s[nb][3] = 0.f;

        #pragma unroll
        for (int c = 0; c < 2; c++) {
            #pragma unroll
            for (int jp = 0; jp < 4; jp++) {
                unsigned kh4[4], kl4[4];
                ldsm4(kh4, &Ks[0][(jp * 16 + brow) * QSTR + c * 16 + bcol]);
                ldsm4(kl4, &Ks[1][(jp * 16 + brow) * QSTR + c * 16 + bcol]);
                mma16816(s[2*jp],   qf[0][c], kh4[0], kh4[1]);
                mma16816(s[2*jp],   qf[1][c], kh4[0], kh4[1]);
                mma16816(s[2*jp],   qf[0][c], kl4[0], kl4[1]);
                mma16816(s[2*jp+1], qf[0][c], kh4[2], kh4[3]);
                mma16816(s[2*jp+1], qf[1][c], kh4[2], kh4[3]);
                mma16816(s[2*jp+1], qf[0][c], kl4[2], kl4[3]);
            }
        }

        // online softmax (rows r=lane/4 and r+8; quad shfl reductions)
        float mx0 = s[0][0], mx1 = s[0][2];
        #pragma unroll
        for (int nb = 0; nb < 8; nb++) {
            mx0 = fmaxf(mx0, fmaxf(s[nb][0], s[nb][1]));
            mx1 = fmaxf(mx1, fmaxf(s[nb][2], s[nb][3]));
        }
        mx0 = fmaxf(mx0, __shfl_xor_sync(~0u, mx0, 1));
        mx0 = fmaxf(mx0, __shfl_xor_sync(~0u, mx0, 2));
        mx1 = fmaxf(mx1, __shfl_xor_sync(~0u, mx1, 1));
        mx1 = fmaxf(mx1, __shfl_xor_sync(~0u, mx1, 2));
        float nm0 = fmaxf(m0r, mx0), nm1 = fmaxf(m1r, mx1);
        float sc0 = __expf(m0r - nm0), sc1 = __expf(m1r - nm1);
        m0r = nm0; m1r = nm1;
        float rs0 = 0.f, rs1 = 0.f;
        #pragma unroll
        for (int nb = 0; nb < 8; nb++) {
            s[nb][0] = __expf(s[nb][0] - nm0);
            s[nb][1] = __expf(s[nb][1] - nm0);
            s[nb][2] = __expf(s[nb][2] - nm1);
            s[nb][3] = __expf(s[nb][3] - nm1);
            rs0 += s[nb][0] + s[nb][1];
            rs1 += s[nb][2] + s[nb][3];
        }
        rs0 += __shfl_xor_sync(~0u, rs0, 1);
        rs0 += __shfl_xor_sync(~0u, rs0, 2);
        rs1 += __shfl_xor_sync(~0u, rs1, 1);
        rs1 += __shfl_xor_sync(~0u, rs1, 2);
        l0 = l0 * sc0 + rs0;  l1 = l1 * sc1 + rs1;
        #pragma unroll
        for (int nb = 0; nb < 4; nb++) {
            oacc[nb][0] *= sc0; oacc[nb][1] *= sc0;
            oacc[nb][2] *= sc1; oacc[nb][3] *= sc1;
        }

        // O += P V  (P split to hi/lo in registers), bf16x3
        #pragma unroll
        for (int c = 0; c < 4; c++) {
            unsigned pah[4], pal[4];
            #pragma unroll
            for (int r4 = 0; r4 < 4; r4++) {
                int nb = 2 * c + (r4 >> 1);
                int pr = (r4 & 1) * 2;
                float x0 = s[nb][pr], x1 = s[nb][pr + 1];
                bf16 h0 = __float2bfloat16(x0);
                bf16 h1 = __float2bfloat16(x1);
                bf16 e0 = __float2bfloat16(x0 - __bfloat162float(h0));
                bf16 e1 = __float2bfloat16(x1 - __bfloat162float(h1));
                pah[r4] = pack2(h0, h1);
                pal[r4] = pack2(e0, e1);
            }
            #pragma unroll
            for (int np = 0; np < 2; np++) {
                unsigned vh4[4], vl4[4];
                ldsm4(vh4, &Vs[0][(np * 16 + brow) * VSTR + c * 16 + bcol]);
                ldsm4(vl4, &Vs[1][(np * 16 + brow) * VSTR + c * 16 + bcol]);
                mma16816(oacc[2*np],   pah, vh4[0], vh4[1]);
                mma16816(oacc[2*np],   pal, vh4[0], vh4[1]);
                mma16816(oacc[2*np],   pah, vl4[0], vl4[1]);
                mma16816(oacc[2*np+1], pah, vh4[2], vh4[3]);
                mma16816(oacc[2*np+1], pal, vh4[2], vh4[3]);
                mma16816(oacc[2*np+1], pah, vl4[2], vl4[3]);
            }
        }
    }

    // epilogue: O / l, write fp32 [b,h,q,d]
    float inv0 = 1.f / l0, inv1 = 1.f / l1;
    int r = lane >> 2;
    int qg = q0 + w * 16 + r;
    size_t ob = (size_t)bh * NQ * HD;
    #pragma unroll
    for (int nb = 0; nb < 4; nb++) {
        int d = nb * 8 + (lane & 3) * 2;
        float2 v0 = make_float2(oacc[nb][0] * inv0, oacc[nb][1] * inv0);
        float2 v1 = make_float2(oacc[nb][2] * inv1, oacc[nb][3] * inv1);
        *(float2*)&O[ob + (size_t)qg * HD + d]       = v0;
        *(float2*)&O[ob + (size_t)(qg + 8) * HD + d] = v1;
    }
}

// ============================== launcher ==================================
extern "C" void kernel_launch(void* const* d_in, const int* in_sizes, int n_in,
                              void* d_out, int out_size)
{
    (void)out_size;
    const float *x=0, *y=0, *wxq=0, *bxq=0, *wyq=0, *byq=0,
                *wpx=0, *bpx=0, *wpy=0, *bpy=0;
    for (int i = 0; i < n_in; i++) {
        const float* p = (const float*)d_in[i];
        switch (in_sizes[i]) {
            case 2097152: x = p;   break;
            case 1048576: y = p;   break;
            case 98304:   wxq = p; break;
            case 196608:  wyq = p; break;
            case 32768:   wpx = p; break;
            case 65536:   wpy = p; break;
            case 256:     bpx = p; break;
            case 512:     bpy = p; break;
            case 384:     if (!bxq) bxq = p; else byq = p; break;
            default: break;
        }
    }
    float* out = (float*)d_out;
    dim3 blk(256);

    gemm_qkv_kernel<<<dim3(HWX/64, 384/64, BATCH), blk>>>(wxq, x, bxq, 0, X_CH, HWX);
    gemm_qkv_kernel<<<dim3(HWY/64, 384/64, BATCH), blk>>>(wyq, y, byq, 1, Y_CH, HWY);

    attn_mma_kernel<<<640, 128>>>();

    gemm_proj_kernel<<<dim3(HWX/64, X_CH/64, BATCH), blk>>>(wpx, bpx, x, out, 0, X_CH, HWX);
    gemm_proj_kernel<<<dim3(HWY/64, Y_CH/64, BATCH), blk>>>(
        wpy, bpy, y, out + (size_t)BATCH*X_CH*HWX, 1, Y_CH, HWY);
}

// round 6
// speedup vs baseline: 2.9437x; 1.0909x over previous
#include <cuda_runtime.h>
#include <cuda_bf16.h>

#define X_CH   256
#define Y_CH   512
#define DIM    128
#define NHEAD  4
#define HD     32
#define HWX    4096
#define HWY    1024
#define BATCH  2
#define GAMMA  0.17677669529663687f   // 32^-0.5

typedef __nv_bfloat16 bf16;

// ---------------- scratch (device globals; no allocation) ----------------
static __device__ __align__(16) bf16 g_qxh[BATCH*NHEAD*HWX*HD], g_qxl[BATCH*NHEAD*HWX*HD];
static __device__ __align__(16) bf16 g_kxh[BATCH*NHEAD*HWX*HD], g_kxl[BATCH*NHEAD*HWX*HD];
static __device__ __align__(16) bf16 g_vxh[BATCH*NHEAD*HWX*HD], g_vxl[BATCH*NHEAD*HWX*HD];
static __device__ __align__(16) bf16 g_qyh[BATCH*NHEAD*HWY*HD], g_qyl[BATCH*NHEAD*HWY*HD];
static __device__ __align__(16) bf16 g_kyh[BATCH*NHEAD*HWY*HD], g_kyl[BATCH*NHEAD*HWY*HD];
static __device__ __align__(16) bf16 g_vyh[BATCH*NHEAD*HWY*HD], g_vyl[BATCH*NHEAD*HWY*HD];
static __device__ float g_ax[BATCH*NHEAD*HWX*HD];   // attention out [b,h,p,d]
static __device__ float g_ay[BATCH*NHEAD*HWY*HD];

__device__ __forceinline__ void bsplit(float v, bf16& h, bf16& l) {
    h = __float2bfloat16(v);
    l = __float2bfloat16(v - __bfloat162float(h));
}

// ============ merged QKV GEMM (fp32, validated round-2 body) ==============
// blocks [0,192): y (K=512, 2x work, scheduled first); [192,960): x.
__global__ void __launch_bounds__(256) gemm_qkv_kernel(
    const float* __restrict__ Wx, const float* __restrict__ Xx, const float* __restrict__ bx,
    const float* __restrict__ Wy, const float* __restrict__ Xy, const float* __restrict__ by_)
{
    bf16 *Qh, *Ql, *Kh, *Kl, *Vh, *Vl;
    const float *W, *X, *bias;
    int KDIM, N, b, m0, n0;
    int blk = blockIdx.x;
    if (blk < 192) {
        KDIM = Y_CH; N = HWY; W = Wy; X = Xy; bias = by_;
        b = blk / 96; int r = blk % 96; m0 = (r % 6) * 64; n0 = (r / 6) * 64;
        Qh=g_qyh; Ql=g_qyl; Kh=g_kyh; Kl=g_kyl; Vh=g_vyh; Vl=g_vyl;
    } else {
        blk -= 192;
        KDIM = X_CH; N = HWX; W = Wx; X = Xx; bias = bx;
        b = blk / 384; int r = blk % 384; m0 = (r % 6) * 64; n0 = (r / 6) * 64;
        Qh=g_qxh; Ql=g_qxl; Kh=g_kxh; Kl=g_kxl; Vh=g_vxh; Vl=g_vxl;
    }

    __shared__ __align__(16) float As[16][64];
    __shared__ __align__(16) float Bs[16][64];

    const float* Xb = X + (size_t)b * KDIM * N;
    const int tid = threadIdx.x;
    const int ty = tid >> 4, tx = tid & 15;
    const int am = tid >> 2, ak = (tid & 3) << 2;
    const int bk = tid >> 4, bn = (tid & 15) << 2;

    float acc[4][4] = {};

    for (int k0 = 0; k0 < KDIM; k0 += 16) {
        float4 av = *(const float4*)(W  + (size_t)(m0 + am) * KDIM + k0 + ak);
        float4 bv = *(const float4*)(Xb + (size_t)(k0 + bk) * N + n0 + bn);
        As[ak+0][am] = av.x; As[ak+1][am] = av.y; As[ak+2][am] = av.z; As[ak+3][am] = av.w;
        *(float4*)(&Bs[bk][bn]) = bv;
        __syncthreads();
        #pragma unroll
        for (int kk = 0; kk < 16; kk++) {
            float4 a4 = *(const float4*)(&As[kk][ty << 2]);
            float4 b4 = *(const float4*)(&Bs[kk][tx << 2]);
            float ar[4] = {a4.x, a4.y, a4.z, a4.w};
            float br[4] = {b4.x, b4.y, b4.z, b4.w};
            #pragma unroll
            for (int i = 0; i < 4; i++)
                #pragma unroll
                for (int j = 0; j < 4; j++)
                    acc[i][j] += ar[i] * br[j];
        }
        __syncthreads();
    }

    #pragma unroll
    for (int i = 0; i < 4; i++) {
        int o = m0 + (ty << 2) + i;          // channel in [0,384)
        float bval = bias[o];
        int t = o >> 7, rch = o & 127, h = rch >> 5, d = rch & 31;
        size_t rb = (size_t)(b * NHEAD + h) * N;
        #pragma unroll
        for (int j = 0; j < 4; j++) {
            int n = n0 + (tx << 2) + j;
            float v = acc[i][j] + bval;
            bf16 hh, ll;
            if (t == 0) {
                bsplit(v * GAMMA, hh, ll);
                Qh[(rb + n) * HD + d] = hh;  Ql[(rb + n) * HD + d] = ll;
            } else if (t == 1) {
                bsplit(v, hh, ll);
                Kh[(rb + n) * HD + d] = hh;  Kl[(rb + n) * HD + d] = ll;
            } else {
                size_t vi = ((size_t)(b * NHEAD + h) * HD + d) * N + n;
                bsplit(v, hh, ll);
                Vh[vi] = hh;  Vl[vi] = ll;
            }
        }
    }
}

// ============ merged proj GEMM (fp32, validated round-2 body) =============
// blocks [0,256): y ; [256,768): x.
__global__ void __launch_bounds__(256) gemm_proj_kernel(
    const float* __restrict__ Wx, const float* __restrict__ bpx, const float* __restrict__ Rx,
    const float* __restrict__ Wy, const float* __restrict__ bpy, const float* __restrict__ Ry,
    float* __restrict__ outp)
{
    const float *W, *bias, *Res, *Att;
    float* Out;
    int OC, N, b, m0, n0;
    int blk = blockIdx.x;
    if (blk < 256) {
        OC = Y_CH; N = HWY; W = Wy; bias = bpy; Res = Ry; Att = g_ay;
        Out = outp + (size_t)BATCH * X_CH * HWX;
        b = blk / 128; int r = blk % 128; m0 = (r % 8) * 64; n0 = (r / 8) * 64;
    } else {
        blk -= 256;
        OC = X_CH; N = HWX; W = Wx; bias = bpx; Res = Rx; Att = g_ax;
        Out = outp;
        b = blk / 256; int r = blk % 256; m0 = (r % 4) * 64; n0 = (r / 4) * 64;
    }

    __shared__ __align__(16) float As[16][64];
    __shared__ __align__(16) float Bs[16][64];

    const int tid = threadIdx.x;
    const int ty = tid >> 4, tx = tid & 15;
    const int am = tid >> 2, ak = (tid & 3) << 2;
    const int bn_ = tid >> 2, bkq = (tid & 3) << 2;

    float acc[4][4] = {};

    for (int k0 = 0; k0 < DIM; k0 += 16) {
        float4 av = *(const float4*)(W + (size_t)(m0 + am) * DIM + k0 + ak);
        int c = k0 + bkq;
        int h = c >> 5, d = c & 31;
        float4 bv = *(const float4*)(Att + ((size_t)(b * NHEAD + h) * N + n0 + bn_) * HD + d);
        As[ak+0][am] = av.x; As[ak+1][am] = av.y; As[ak+2][am] = av.z; As[ak+3][am] = av.w;
        Bs[bkq+0][bn_] = bv.x; Bs[bkq+1][bn_] = bv.y; Bs[bkq+2][bn_] = bv.z; Bs[bkq+3][bn_] = bv.w;
        __syncthreads();
        #pragma unroll
        for (int kk = 0; kk < 16; kk++) {
            float4 a4 = *(const float4*)(&As[kk][ty << 2]);
            float4 b4 = *(const float4*)(&Bs[kk][tx << 2]);
            float ar[4] = {a4.x, a4.y, a4.z, a4.w};
            float br[4] = {b4.x, b4.y, b4.z, b4.w};
            #pragma unroll
            for (int i = 0; i < 4; i++)
                #pragma unroll
                for (int j = 0; j < 4; j++)
                    acc[i][j] += ar[i] * br[j];
        }
        __syncthreads();
    }

    #pragma unroll
    for (int i = 0; i < 4; i++) {
        int o = m0 + (ty << 2) + i;
        float bval = bias[o];
        size_t off = ((size_t)b * OC + o) * N + n0 + (tx << 2);
        float4 rr = *(const float4*)(Res + off);
        float4 v;
        v.x = acc[i][0] + bval + rr.x;
        v.y = acc[i][1] + bval + rr.y;
        v.z = acc[i][2] + bval + rr.z;
        v.w = acc[i][3] + bval + rr.w;
        *(float4*)(Out + off) = v;
    }
}

// ================= MMA flash attention, cp.async pipelined =================
__device__ __forceinline__ void ldsm4(unsigned r[4], const void* p) {
    unsigned a = (unsigned)__cvta_generic_to_shared(p);
    asm volatile("ldmatrix.sync.aligned.m8n8.x4.shared.b16 {%0,%1,%2,%3}, [%4];"
        : "=r"(r[0]), "=r"(r[1]), "=r"(r[2]), "=r"(r[3]) : "r"(a));
}
__device__ __forceinline__ void mma16816(float c[4], const unsigned a[4],
                                         unsigned b0, unsigned b1) {
    asm volatile("mma.sync.aligned.m16n8k16.row.col.f32.bf16.bf16.f32 "
        "{%0,%1,%2,%3}, {%4,%5,%6,%7}, {%8,%9}, {%0,%1,%2,%3};"
        : "+f"(c[0]), "+f"(c[1]), "+f"(c[2]), "+f"(c[3])
        : "r"(a[0]), "r"(a[1]), "r"(a[2]), "r"(a[3]), "r"(b0), "r"(b1));
}
__device__ __forceinline__ unsigned pack2(bf16 a, bf16 b) {
    return (unsigned)__bfloat16_as_ushort(a) | ((unsigned)__bfloat16_as_ushort(b) << 16);
}
__device__ __forceinline__ void cpasync16(unsigned dst, const void* src) {
    asm volatile("cp.async.ca.shared.global [%0], [%1], 16;" :: "r"(dst), "l"(src));
}

#define QSTR 40
#define VSTR 72
// per-stage bf16 element offsets inside KV[s]
#define OFF_KH 0
#define OFF_KL 2560
#define OFF_VH 5120
#define OFF_VL 7424
#define STAGE_ELEMS 9728

// 64 queries/block, 4 warps, KV tile 64 keys, 2-stage cp.async pipeline.
// blocks [0,128): y attends x (long, first); [128,640): x attends y.
__global__ void __launch_bounds__(128) attn_mma_kernel()
{
    __shared__ __align__(16) bf16 KV[2][STAGE_ELEMS];

    int blk = blockIdx.x;
    const bf16 *Qh, *Ql, *Kh, *Kl, *Vh, *Vl; float* O;
    int NQ, NK, bh, q0;
    if (blk < 128) {   // dir1: y attends x
        bh = blk >> 4; q0 = (blk & 15) * 64; NQ = HWY; NK = HWX;
        Qh=g_qyh; Ql=g_qyl; Kh=g_kxh; Kl=g_kxl; Vh=g_vxh; Vl=g_vxl; O=g_ay;
    } else {           // dir0: x attends y
        blk -= 128;
        bh = blk >> 6; q0 = (blk & 63) * 64; NQ = HWX; NK = HWY;
        Qh=g_qxh; Ql=g_qxl; Kh=g_kyh; Kl=g_kyl; Vh=g_vyh; Vl=g_vyl; O=g_ax;
    }

    const int tid = threadIdx.x, w = tid >> 5, lane = tid & 31;
    const size_t kbase = (size_t)bh * NK * HD;
    const size_t vbase = (size_t)bh * HD * NK;
    const int nt = NK >> 6;

    // per-thread load geometry (two 8-element chunks per buffer)
    const int e0 = tid * 8, e1 = (tid + 128) * 8;
    const int ks0 = (e0 >> 5) * QSTR + (e0 & 31);
    const int ks1 = (e1 >> 5) * QSTR + (e1 & 31);
    const int vs0 = (e0 >> 6) * VSTR + (e0 & 63);
    const int vs1 = (e1 >> 6) * VSTR + (e1 & 63);
    const size_t kg0 = (size_t)(e0 >> 5) * HD + (e0 & 31);
    const size_t kg1 = (size_t)(e1 >> 5) * HD + (e1 & 31);
    const size_t vg0 = (size_t)(e0 >> 6) * NK + (e0 & 63);
    const size_t vg1 = (size_t)(e1 >> 6) * NK + (e1 & 63);

    unsigned sb0 = (unsigned)__cvta_generic_to_shared(&KV[0][0]);
    unsigned sb1 = (unsigned)__cvta_generic_to_shared(&KV[1][0]);

    // ---- issue tile 0 into stage 0 (overlaps Q staging below) ----
    {
        size_t ka = kbase, va = vbase;
        cpasync16(sb0 + (OFF_KH + ks0) * 2, Kh + ka + kg0);
        cpasync16(sb0 + (OFF_KH + ks1) * 2, Kh + ka + kg1);
        cpasync16(sb0 + (OFF_KL + ks0) * 2, Kl + ka + kg0);
        cpasync16(sb0 + (OFF_KL + ks1) * 2, Kl + ka + kg1);
        cpasync16(sb0 + (OFF_VH + vs0) * 2, Vh + va + vg0);
        cpasync16(sb0 + (OFF_VH + vs1) * 2, Vh + va + vg1);
        cpasync16(sb0 + (OFF_VL + vs0) * 2, Vl + va + vg0);
        cpasync16(sb0 + (OFF_VL + vs1) * 2, Vl + va + vg1);
        asm volatile("cp.async.commit_group;");
    }

    // ---- stage Q (hi+lo) in stage-1 buffer, extract fragments ----
    {
        bf16* Qsh = &KV[1][0];
        bf16* Qsl = &KV[1][2560];
        const size_t qb = (size_t)bh * NQ * HD + (size_t)q0 * HD;
        #pragma unroll
        for (int it = 0; it < 2; it++) {
            int e = (tid + it * 128) * 8;
            int row = e >> 5, col = e & 31;
            *(uint4*)&Qsh[row * QSTR + col] = *(const uint4*)(Qh + qb + (size_t)row * HD + col);
            *(uint4*)&Qsl[row * QSTR + col] = *(const uint4*)(Ql + qb + (size_t)row * HD + col);
        }
    }
    __syncthreads();

    const int arow = (lane & 7) + ((lane & 8) ? 8 : 0);
    const int acol = (lane & 16) ? 8 : 0;
    const int brow = (lane & 7) + ((lane & 16) ? 8 : 0);
    const int bcol = (lane & 8) ? 8 : 0;
    unsigned qf[2][2][4];
    #pragma unroll
    for (int p = 0; p < 2; p++)
        #pragma unroll
        for (int c = 0; c < 2; c++)
            ldsm4(qf[p][c], &KV[1][p * 2560 + (w * 16 + arow) * QSTR + c * 16 + acol]);
    __syncthreads();   // Q reads done before stage-1 gets refilled

    float m0r = -1e30f, m1r = -1e30f, l0 = 0.f, l1 = 0.f;
    float oacc[4][4] = {};

    for (int kt = 0; kt < nt; kt++) {
        const int s = kt & 1;
        if (kt + 1 < nt) {
            unsigned sb = (s ^ 1) ? sb1 : sb0;
            size_t ka = kbase + (size_t)(kt + 1) * 64 * HD;
            size_t va = vbase + (size_t)(kt + 1) * 64;
            cpasync16(sb + (OFF_KH + ks0) * 2, Kh + ka + kg0);
            cpasync16(sb + (OFF_KH + ks1) * 2, Kh + ka + kg1);
            cpasync16(sb + (OFF_KL + ks0) * 2, Kl + ka + kg0);
            cpasync16(sb + (OFF_KL + ks1) * 2, Kl + ka + kg1);
            cpasync16(sb + (OFF_VH + vs0) * 2, Vh + va + vg0);
            cpasync16(sb + (OFF_VH + vs1) * 2, Vh + va + vg1);
            cpasync16(sb + (OFF_VL + vs0) * 2, Vl + va + vg0);
            cpasync16(sb + (OFF_VL + vs1) * 2, Vl + va + vg1);
            asm volatile("cp.async.commit_group;");
            asm volatile("cp.async.wait_group 1;" ::: "memory");
        } else {
            asm volatile("cp.async.wait_group 0;" ::: "memory");
        }
        __syncthreads();

        const bf16* Ks0 = &KV[s][OFF_KH];
        const bf16* Ks1 = &KV[s][OFF_KL];
        const bf16* Vs0 = &KV[s][OFF_VH];
        const bf16* Vs1 = &KV[s][OFF_VL];

        // S = Q K^T  (16q x 64keys per warp), bf16x3
        float sreg[8][4];
        #pragma unroll
        for (int nb = 0; nb < 8; nb++)
            sreg[nb][0] = sreg[nb][1] = sreg[nb][2] = sreg[nb][3] = 0.f;

        #pragma unroll
        for (int c = 0; c < 2; c++) {
            #pragma unroll
            for (int jp = 0; jp < 4; jp++) {
                unsigned kh4[4], kl4[4];
                ldsm4(kh4, &Ks0[(jp * 16 + brow) * QSTR + c * 16 + bcol]);
                ldsm4(kl4, &Ks1[(jp * 16 + brow) * QSTR + c * 16 + bcol]);
                mma16816(sreg[2*jp],   qf[0][c], kh4[0], kh4[1]);
                mma16816(sreg[2*jp],   qf[1][c], kh4[0], kh4[1]);
                mma16816(sreg[2*jp],   qf[0][c], kl4[0], kl4[1]);
                mma16816(sreg[2*jp+1], qf[0][c], kh4[2], kh4[3]);
                mma16816(sreg[2*jp+1], qf[1][c], kh4[2], kh4[3]);
                mma16816(sreg[2*jp+1], qf[0][c], kl4[2], kl4[3]);
            }
        }

        // online softmax
        float mx0 = sreg[0][0], mx1 = sreg[0][2];
        #pragma unroll
        for (int nb = 0; nb < 8; nb++) {
            mx0 = fmaxf(mx0, fmaxf(sreg[nb][0], sreg[nb][1]));
            mx1 = fmaxf(mx1, fmaxf(sreg[nb][2], sreg[nb][3]));
        }
        mx0 = fmaxf(mx0, __shfl_xor_sync(~0u, mx0, 1));
        mx0 = fmaxf(mx0, __shfl_xor_sync(~0u, mx0, 2));
        mx1 = fmaxf(mx1, __shfl_xor_sync(~0u, mx1, 1));
        mx1 = fmaxf(mx1, __shfl_xor_sync(~0u, mx1, 2));
        float nm0 = fmaxf(m0r, mx0), nm1 = fmaxf(m1r, mx1);
        float sc0 = __expf(m0r - nm0), sc1 = __expf(m1r - nm1);
        m0r = nm0; m1r = nm1;
        float rs0 = 0.f, rs1 = 0.f;
        #pragma unroll
        for (int nb = 0; nb < 8; nb++) {
            sreg[nb][0] = __expf(sreg[nb][0] - nm0);
            sreg[nb][1] = __expf(sreg[nb][1] - nm0);
            sreg[nb][2] = __expf(sreg[nb][2] - nm1);
            sreg[nb][3] = __expf(sreg[nb][3] - nm1);
            rs0 += sreg[nb][0] + sreg[nb][1];
            rs1 += sreg[nb][2] + sreg[nb][3];
        }
        rs0 += __shfl_xor_sync(~0u, rs0, 1);
        rs0 += __shfl_xor_sync(~0u, rs0, 2);
        rs1 += __shfl_xor_sync(~0u, rs1, 1);
        rs1 += __shfl_xor_sync(~0u, rs1, 2);
        l0 = l0 * sc0 + rs0;  l1 = l1 * sc1 + rs1;
        #pragma unroll
        for (int nb = 0; nb < 4; nb++) {
            oacc[nb][0] *= sc0; oacc[nb][1] *= sc0;
            oacc[nb][2] *= sc1; oacc[nb][3] *= sc1;
        }

        // O += P V  (P split hi/lo in registers), bf16x3
        #pragma unroll
        for (int c = 0; c < 4; c++) {
            unsigned pah[4], pal[4];
            #pragma unroll
            for (int r4 = 0; r4 < 4; r4++) {
                int nb = 2 * c + (r4 >> 1);
                int pr = (r4 & 1) * 2;
                float x0 = sreg[nb][pr], x1 = sreg[nb][pr + 1];
                bf16 h0 = __float2bfloat16(x0);
                bf16 h1 = __float2bfloat16(x1);
                bf16 e0b = __float2bfloat16(x0 - __bfloat162float(h0));
                bf16 e1b = __float2bfloat16(x1 - __bfloat162float(h1));
                pah[r4] = pack2(h0, h1);
                pal[r4] = pack2(e0b, e1b);
            }
            #pragma unroll
            for (int np = 0; np < 2; np++) {
                unsigned vh4[4], vl4[4];
                ldsm4(vh4, &Vs0[(np * 16 + brow) * VSTR + c * 16 + bcol]);
                ldsm4(vl4, &Vs1[(np * 16 + brow) * VSTR + c * 16 + bcol]);
                mma16816(oacc[2*np],   pah, vh4[0], vh4[1]);
                mma16816(oacc[2*np],   pal, vh4[0], vh4[1]);
                mma16816(oacc[2*np],   pah, vl4[0], vl4[1]);
                mma16816(oacc[2*np+1], pah, vh4[2], vh4[3]);
                mma16816(oacc[2*np+1], pal, vh4[2], vh4[3]);
                mma16816(oacc[2*np+1], pah, vl4[2], vl4[3]);
            }
        }
        __syncthreads();   // all reads of stage s done before it is refilled
    }

    // epilogue: O / l, write fp32 [b,h,q,d]
    float inv0 = 1.f / l0, inv1 = 1.f / l1;
    int r = lane >> 2;
    int qg = q0 + w * 16 + r;
    size_t ob = (size_t)bh * NQ * HD;
    #pragma unroll
    for (int nb = 0; nb < 4; nb++) {
        int d = nb * 8 + (lane & 3) * 2;
        float2 v0 = make_float2(oacc[nb][0] * inv0, oacc[nb][1] * inv0);
        float2 v1 = make_float2(oacc[nb][2] * inv1, oacc[nb][3] * inv1);
        *(float2*)&O[ob + (size_t)qg * HD + d]       = v0;
        *(float2*)&O[ob + (size_t)(qg + 8) * HD + d] = v1;
    }
}

// ============================== launcher ==================================
extern "C" void kernel_launch(void* const* d_in, const int* in_sizes, int n_in,
                              void* d_out, int out_size)
{
    (void)out_size;
    const float *x=0, *y=0, *wxq=0, *bxq=0, *wyq=0, *byq=0,
                *wpx=0, *bpx=0, *wpy=0, *bpy=0;
    for (int i = 0; i < n_in; i++) {
        const float* p = (const float*)d_in[i];
        switch (in_sizes[i]) {
            case 2097152: x = p;   break;
            case 1048576: y = p;   break;
            case 98304:   wxq = p; break;
            case 196608:  wyq = p; break;
            case 32768:   wpx = p; break;
            case 65536:   wpy = p; break;
            case 256:     bpx = p; break;
            case 512:     bpy = p; break;
            case 384:     if (!bxq) bxq = p; else byq = p; break;
            default: break;
        }
    }
    float* out = (float*)d_out;

    gemm_qkv_kernel<<<960, 256>>>(wxq, x, bxq, wyq, y, byq);
    attn_mma_kernel<<<640, 128>>>();
    gemm_proj_kernel<<<768, 256>>>(wpx, bpx, x, wpy, bpy, y, out);
}

// round 7
// speedup vs baseline: 3.0400x; 1.0327x over previous
#include <cuda_runtime.h>
#include <cuda_bf16.h>

#define X_CH   256
#define Y_CH   512
#define DIM    128
#define NHEAD  4
#define HD     32
#define HWX    4096
#define HWY    1024
#define BATCH  2
#define GAMMA  0.17677669529663687f   // 32^-0.5

typedef __nv_bfloat16 bf16;

// ---------------- scratch (device globals; no allocation) ----------------
static __device__ __align__(16) bf16 g_qxh[BATCH*NHEAD*HWX*HD], g_qxl[BATCH*NHEAD*HWX*HD];
static __device__ __align__(16) bf16 g_kxh[BATCH*NHEAD*HWX*HD], g_kxl[BATCH*NHEAD*HWX*HD];
static __device__ __align__(16) bf16 g_vxh[BATCH*NHEAD*HWX*HD], g_vxl[BATCH*NHEAD*HWX*HD];
static __device__ __align__(16) bf16 g_qyh[BATCH*NHEAD*HWY*HD], g_qyl[BATCH*NHEAD*HWY*HD];
static __device__ __align__(16) bf16 g_kyh[BATCH*NHEAD*HWY*HD], g_kyl[BATCH*NHEAD*HWY*HD];
static __device__ __align__(16) bf16 g_vyh[BATCH*NHEAD*HWY*HD], g_vyl[BATCH*NHEAD*HWY*HD];
static __device__ float g_ax[BATCH*NHEAD*HWX*HD];   // attention out [b,h,p,d]
static __device__ float g_ay[BATCH*NHEAD*HWY*HD];

__device__ __forceinline__ void bsplit(float v, bf16& h, bf16& l) {
    h = __float2bfloat16(v);
    l = __float2bfloat16(v - __bfloat162float(h));
}
__device__ __forceinline__ unsigned pack2(bf16 a, bf16 b) {
    return (unsigned)__bfloat16_as_ushort(a) | ((unsigned)__bfloat16_as_ushort(b) << 16);
}

// ---------------- MMA helpers ----------------
__device__ __forceinline__ void ldsm4(unsigned r[4], const void* p) {
    unsigned a = (unsigned)__cvta_generic_to_shared(p);
    asm volatile("ldmatrix.sync.aligned.m8n8.x4.shared.b16 {%0,%1,%2,%3}, [%4];"
        : "=r"(r[0]), "=r"(r[1]), "=r"(r[2]), "=r"(r[3]) : "r"(a));
}
__device__ __forceinline__ void ldsm4t(unsigned r[4], const void* p) {
    unsigned a = (unsigned)__cvta_generic_to_shared(p);
    asm volatile("ldmatrix.sync.aligned.m8n8.x4.trans.shared.b16 {%0,%1,%2,%3}, [%4];"
        : "=r"(r[0]), "=r"(r[1]), "=r"(r[2]), "=r"(r[3]) : "r"(a));
}
__device__ __forceinline__ void mma16816(float c[4], const unsigned a[4],
                                         unsigned b0, unsigned b1) {
    asm volatile("mma.sync.aligned.m16n8k16.row.col.f32.bf16.bf16.f32 "
        "{%0,%1,%2,%3}, {%4,%5,%6,%7}, {%8,%9}, {%0,%1,%2,%3};"
        : "+f"(c[0]), "+f"(c[1]), "+f"(c[2]), "+f"(c[3])
        : "r"(a[0]), "r"(a[1]), "r"(a[2]), "r"(a[3]), "r"(b0), "r"(b1));
}

#define GSTR 40    // A tile row stride (bf16), [m][k] layout
#define BSTR 136   // B tile row stride (bf16), [k][n] natural layout

// ============ QKV tensor-core GEMM v2 (bf16x3, inline split, no prep) =====
// C[384,N] = W[384,K] * X[K,N] + bias; 128x128 tiles, 8 warps (4m x 2n).
// blocks [0,48): y (K=512, scheduled first); [48,240): x.
__global__ void __launch_bounds__(256) qkv_mma2_kernel(
    const float* __restrict__ Wx, const float* __restrict__ Xx, const float* __restrict__ bx,
    const float* __restrict__ Wy, const float* __restrict__ Xy, const float* __restrict__ by_)
{
    // As0/As1: 128*40 bf16 each; Bs0/Bs1: 32*136 bf16 each; total 37888 B.
    // Cst (64*128 fp32 = 32768 B) aliases the same storage after the mainloop.
    __shared__ __align__(16) char SMB[37888];
    bf16* As0 = (bf16*)SMB;
    bf16* As1 = As0 + 128*GSTR;
    bf16* Bs0 = As1 + 128*GSTR;
    bf16* Bs1 = Bs0 + 32*BSTR;
    float* Cst = (float*)SMB;

    const float *W, *X, *bias;
    bf16 *Qh_, *Ql_, *Kh_, *Kl_, *Vh_, *Vl_;
    int N, K, m0, n0, b;
    int blk = blockIdx.x;
    if (blk < 48) {                       // y: 2b x 3m x 8n
        N = HWY; K = Y_CH;
        b = blk / 24; int r = blk % 24; m0 = (r % 3) * 128; n0 = (r / 3) * 128;
        W = Wy; X = Xy + (size_t)b * K * N; bias = by_;
        Qh_=g_qyh; Ql_=g_qyl; Kh_=g_kyh; Kl_=g_kyl; Vh_=g_vyh; Vl_=g_vyl;
    } else {                              // x: 2b x 3m x 32n
        blk -= 48;
        N = HWX; K = X_CH;
        b = blk / 96; int r = blk % 96; m0 = (r % 3) * 128; n0 = (r / 3) * 128;
        W = Wx; X = Xx + (size_t)b * K * N; bias = bx;
        Qh_=g_qxh; Ql_=g_qxl; Kh_=g_kxh; Kl_=g_kxl; Vh_=g_vxh; Vl_=g_vxl;
    }

    const int tid = threadIdx.x, lane = tid & 31;
    const int w = tid >> 5;
    const int wm = w & 3, wn = w >> 2;
    // A-fragment ldsm geometry (validated via attention Q path)
    const int arow = (lane & 7) + ((lane & 8) ? 8 : 0);
    const int acol = (lane & 16) ? 8 : 0;
    // B-fragment (trans) geometry: stored [k][n]; lanes 0-7 m0(k0-7,n0-7),
    // 8-15 m1(k8-15,n0-7), 16-23 m2(k0-7,n8-15), 24-31 m3(k8-15,n8-15)
    const int bkrow = (lane & 7) + ((lane & 8) ? 8 : 0);
    const int bncol = (lane & 16) ? 8 : 0;

    float acc[2][8][4] = {};

    const int nkc = K >> 5;
    for (int kc = 0; kc < nkc; kc++) {
        __syncthreads();
        // ---- stage A tile: W[128m x 32k], inline fp32 -> split bf16 ----
        #pragma unroll
        for (int it = 0; it < 4; it++) {
            int f = (tid + it * 256) * 4;       // 0..4095
            int row = f >> 5, col = f & 31;
            float4 wv = *(const float4*)(W + (size_t)(m0 + row) * K + kc * 32 + col);
            bf16 h0,l0,h1,l1,h2,l2,h3,l3;
            bsplit(wv.x,h0,l0); bsplit(wv.y,h1,l1);
            bsplit(wv.z,h2,l2); bsplit(wv.w,h3,l3);
            *(uint2*)&As0[row * GSTR + col] = make_uint2(pack2(h0,h1), pack2(h2,h3));
            *(uint2*)&As1[row * GSTR + col] = make_uint2(pack2(l0,l1), pack2(l2,l3));
        }
        // ---- stage B tile: X[32k x 128n] natural layout, inline split ----
        #pragma unroll
        for (int it = 0; it < 4; it++) {
            int f = (tid + it * 256) * 4;
            int kk = f >> 7, nn = f & 127;
            float4 xv = *(const float4*)(X + (size_t)(kc * 32 + kk) * N + n0 + nn);
            bf16 h0,l0,h1,l1,h2,l2,h3,l3;
            bsplit(xv.x,h0,l0); bsplit(xv.y,h1,l1);
            bsplit(xv.z,h2,l2); bsplit(xv.w,h3,l3);
            *(uint2*)&Bs0[kk * BSTR + nn] = make_uint2(pack2(h0,h1), pack2(h2,h3));
            *(uint2*)&Bs1[kk * BSTR + nn] = make_uint2(pack2(l0,l1), pack2(l2,l3));
        }
        __syncthreads();

        #pragma unroll
        for (int ks = 0; ks < 2; ks++) {
            unsigned ah[2][4], al[2][4];
            #pragma unroll
            for (int im = 0; im < 2; im++) {
                ldsm4(ah[im], &As0[(wm*32 + im*16 + arow) * GSTR + ks*16 + acol]);
                ldsm4(al[im], &As1[(wm*32 + im*16 + arow) * GSTR + ks*16 + acol]);
            }
            #pragma unroll
            for (int jn = 0; jn < 4; jn++) {
                unsigned bh4[4], bl4[4];
                const int boff = (ks*16 + bkrow) * BSTR + wn*64 + jn*16 + bncol;
                ldsm4t(bh4, &Bs0[boff]);
                ldsm4t(bl4, &Bs1[boff]);
                #pragma unroll
                for (int im = 0; im < 2; im++) {
                    mma16816(acc[im][2*jn],   ah[im], bh4[0], bh4[1]);
                    mma16816(acc[im][2*jn],   al[im], bh4[0], bh4[1]);
                    mma16816(acc[im][2*jn],   ah[im], bl4[0], bl4[1]);
                    mma16816(acc[im][2*jn+1], ah[im], bh4[2], bh4[3]);
                    mma16816(acc[im][2*jn+1], al[im], bh4[2], bh4[3]);
                    mma16816(acc[im][2*jn+1], ah[im], bl4[2], bl4[3]);
                }
            }
        }
    }

    // ---- staged epilogue: fragments -> smem fp32 -> linear scatter ----
    const int r = lane >> 2, cq = (lane & 3) * 2;
    #pragma unroll
    for (int im = 0; im < 2; im++) {
        __syncthreads();
        #pragma unroll
        for (int j8 = 0; j8 < 8; j8++) {
            int col = wn*64 + j8*8 + cq;
            Cst[(wm*16 + r) * 128 + col]         = acc[im][j8][0];
            Cst[(wm*16 + r) * 128 + col + 1]     = acc[im][j8][1];
            Cst[(wm*16 + r + 8) * 128 + col]     = acc[im][j8][2];
            Cst[(wm*16 + r + 8) * 128 + col + 1] = acc[im][j8][3];
        }
        __syncthreads();
        for (int idx = tid; idx < 64*128; idx += 256) {
            int srow = idx >> 7, scol = idx & 127;
            int o = m0 + (srow >> 4) * 32 + im*16 + (srow & 15);
            int n = n0 + scol;
            float v = Cst[idx] + bias[o];
            int t = o >> 7, h = (o & 127) >> 5, d = o & 31;
            bf16 hh, ll;
            if (t == 0) {
                bsplit(v * GAMMA, hh, ll);
                size_t i2 = ((size_t)(b*NHEAD + h) * N + n) * HD + d;
                Qh_[i2] = hh;  Ql_[i2] = ll;
            } else if (t == 1) {
                bsplit(v, hh, ll);
                size_t i2 = ((size_t)(b*NHEAD + h) * N + n) * HD + d;
                Kh_[i2] = hh;  Kl_[i2] = ll;
            } else {
                bsplit(v, hh, ll);
                size_t i2 = ((size_t)(b*NHEAD + h) * HD + d) * N + n;
                Vh_[i2] = hh;  Vl_[i2] = ll;
            }
        }
    }
}

// ============ merged proj GEMM (fp32, validated round-6) ==================
__global__ void __launch_bounds__(256) gemm_proj_kernel(
    const float* __restrict__ Wx, const float* __restrict__ bpx, const float* __restrict__ Rx,
    const float* __restrict__ Wy, const float* __restrict__ bpy, const float* __restrict__ Ry,
    float* __restrict__ outp)
{
    const float *W, *bias, *Res, *Att;
    float* Out;
    int OC, N, b, m0, n0;
    int blk = blockIdx.x;
    if (blk < 256) {
        OC = Y_CH; N = HWY; W = Wy; bias = bpy; Res = Ry; Att = g_ay;
        Out = outp + (size_t)BATCH * X_CH * HWX;
        b = blk / 128; int r = blk % 128; m0 = (r % 8) * 64; n0 = (r / 8) * 64;
    } else {
        blk -= 256;
        OC = X_CH; N = HWX; W = Wx; bias = bpx; Res = Rx; Att = g_ax;
        Out = outp;
        b = blk / 256; int r = blk % 256; m0 = (r % 4) * 64; n0 = (r / 4) * 64;
    }

    __shared__ __align__(16) float As[16][64];
    __shared__ __align__(16) float Bs[16][64];

    const int tid = threadIdx.x;
    const int ty = tid >> 4, tx = tid & 15;
    const int am = tid >> 2, ak = (tid & 3) << 2;
    const int bn_ = tid >> 2, bkq = (tid & 3) << 2;

    float acc[4][4] = {};

    for (int k0 = 0; k0 < DIM; k0 += 16) {
        float4 av = *(const float4*)(W + (size_t)(m0 + am) * DIM + k0 + ak);
        int c = k0 + bkq;
        int h = c >> 5, d = c & 31;
        float4 bv = *(const float4*)(Att + ((size_t)(b * NHEAD + h) * N + n0 + bn_) * HD + d);
        As[ak+0][am] = av.x; As[ak+1][am] = av.y; As[ak+2][am] = av.z; As[ak+3][am] = av.w;
        Bs[bkq+0][bn_] = bv.x; Bs[bkq+1][bn_] = bv.y; Bs[bkq+2][bn_] = bv.z; Bs[bkq+3][bn_] = bv.w;
        __syncthreads();
        #pragma unroll
        for (int kk = 0; kk < 16; kk++) {
            float4 a4 = *(const float4*)(&As[kk][ty << 2]);
            float4 b4 = *(const float4*)(&Bs[kk][tx << 2]);
            float ar[4] = {a4.x, a4.y, a4.z, a4.w};
            float br[4] = {b4.x, b4.y, b4.z, b4.w};
            #pragma unroll
            for (int i = 0; i < 4; i++)
                #pragma unroll
                for (int j = 0; j < 4; j++)
                    acc[i][j] += ar[i] * br[j];
        }
        __syncthreads();
    }

    #pragma unroll
    for (int i = 0; i < 4; i++) {
        int o = m0 + (ty << 2) + i;
        float bval = bias[o];
        size_t off = ((size_t)b * OC + o) * N + n0 + (tx << 2);
        float4 rr = *(const float4*)(Res + off);
        float4 v;
        v.x = acc[i][0] + bval + rr.x;
        v.y = acc[i][1] + bval + rr.y;
        v.z = acc[i][2] + bval + rr.z;
        v.w = acc[i][3] + bval + rr.w;
        *(float4*)(Out + off) = v;
    }
}

// ================= MMA flash attention, cp.async (round-6 validated) =======
__device__ __forceinline__ void cpasync16(unsigned dst, const void* src) {
    asm volatile("cp.async.ca.shared.global [%0], [%1], 16;" :: "r"(dst), "l"(src));
}

#define QSTR 40
#define VSTR 72
#define OFF_KH 0
#define OFF_KL 2560
#define OFF_VH 5120
#define OFF_VL 7424
#define STAGE_ELEMS 9728

__global__ void __launch_bounds__(128) attn_mma_kernel()
{
    __shared__ __align__(16) bf16 KV[2][STAGE_ELEMS];

    int blk = blockIdx.x;
    const bf16 *Qh, *Ql, *Kh, *Kl, *Vh, *Vl; float* O;
    int NQ, NK, bh, q0;
    if (blk < 128) {   // dir1: y attends x
        bh = blk >> 4; q0 = (blk & 15) * 64; NQ = HWY; NK = HWX;
        Qh=g_qyh; Ql=g_qyl; Kh=g_kxh; Kl=g_kxl; Vh=g_vxh; Vl=g_vxl; O=g_ay;
    } else {           // dir0: x attends y
        blk -= 128;
        bh = blk >> 6; q0 = (blk & 63) * 64; NQ = HWX; NK = HWY;
        Qh=g_qxh; Ql=g_qxl; Kh=g_kyh; Kl=g_kyl; Vh=g_vyh; Vl=g_vyl; O=g_ax;
    }

    const int tid = threadIdx.x, w = tid >> 5, lane = tid & 31;
    const size_t kbase = (size_t)bh * NK * HD;
    const size_t vbase = (size_t)bh * HD * NK;
    const int nt = NK >> 6;

    const int e0 = tid * 8, e1 = (tid + 128) * 8;
    const int ks0 = (e0 >> 5) * QSTR + (e0 & 31);
    const int ks1 = (e1 >> 5) * QSTR + (e1 & 31);
    const int vs0 = (e0 >> 6) * VSTR + (e0 & 63);
    const int vs1 = (e1 >> 6) * VSTR + (e1 & 63);
    const size_t kg0 = (size_t)(e0 >> 5) * HD + (e0 & 31);
    const size_t kg1 = (size_t)(e1 >> 5) * HD + (e1 & 31);
    const size_t vg0 = (size_t)(e0 >> 6) * NK + (e0 & 63);
    const size_t vg1 = (size_t)(e1 >> 6) * NK + (e1 & 63);

    unsigned sb0 = (unsigned)__cvta_generic_to_shared(&KV[0][0]);
    unsigned sb1 = (unsigned)__cvta_generic_to_shared(&KV[1][0]);

    {
        size_t ka = kbase, va = vbase;
        cpasync16(sb0 + (OFF_KH + ks0) * 2, Kh + ka + kg0);
        cpasync16(sb0 + (OFF_KH + ks1) * 2, Kh + ka + kg1);
        cpasync16(sb0 + (OFF_KL + ks0) * 2, Kl + ka + kg0);
        cpasync16(sb0 + (OFF_KL + ks1) * 2, Kl + ka + kg1);
        cpasync16(sb0 + (OFF_VH + vs0) * 2, Vh + va + vg0);
        cpasync16(sb0 + (OFF_VH + vs1) * 2, Vh + va + vg1);
        cpasync16(sb0 + (OFF_VL + vs0) * 2, Vl + va + vg0);
        cpasync16(sb0 + (OFF_VL + vs1) * 2, Vl + va + vg1);
        asm volatile("cp.async.commit_group;");
    }

    {
        bf16* Qsh = &KV[1][0];
        bf16* Qsl = &KV[1][2560];
        const size_t qb = (size_t)bh * NQ * HD + (size_t)q0 * HD;
        #pragma unroll
        for (int it = 0; it < 2; it++) {
            int e = (tid + it * 128) * 8;
            int row = e >> 5, col = e & 31;
            *(uint4*)&Qsh[row * QSTR + col] = *(const uint4*)(Qh + qb + (size_t)row * HD + col);
            *(uint4*)&Qsl[row * QSTR + col] = *(const uint4*)(Ql + qb + (size_t)row * HD + col);
        }
    }
    __syncthreads();

    const int arow = (lane & 7) + ((lane & 8) ? 8 : 0);
    const int acol = (lane & 16) ? 8 : 0;
    const int brow = (lane & 7) + ((lane & 16) ? 8 : 0);
    const int bcol = (lane & 8) ? 8 : 0;
    unsigned qf[2][2][4];
    #pragma unroll
    for (int p = 0; p < 2; p++)
        #pragma unroll
        for (int c = 0; c < 2; c++)
            ldsm4(qf[p][c], &KV[1][p * 2560 + (w * 16 + arow) * QSTR + c * 16 + acol]);
    __syncthreads();

    float m0r = -1e30f, m1r = -1e30f, l0 = 0.f, l1 = 0.f;
    float oacc[4][4] = {};

    for (int kt = 0; kt < nt; kt++) {
        const int s = kt & 1;
        if (kt + 1 < nt) {
            unsigned sb = (s ^ 1) ? sb1 : sb0;
            size_t ka = kbase + (size_t)(kt + 1) * 64 * HD;
            size_t va = vbase + (size_t)(kt + 1) * 64;
            cpasync16(sb + (OFF_KH + ks0) * 2, Kh + ka + kg0);
            cpasync16(sb + (OFF_KH + ks1) * 2, Kh + ka + kg1);
            cpasync16(sb + (OFF_KL + ks0) * 2, Kl + ka + kg0);
            cpasync16(sb + (OFF_KL + ks1) * 2, Kl + ka + kg1);
            cpasync16(sb + (OFF_VH + vs0) * 2, Vh + va + vg0);
            cpasync16(sb + (OFF_VH + vs1) * 2, Vh + va + vg1);
            cpasync16(sb + (OFF_VL + vs0) * 2, Vl + va + vg0);
            cpasync16(sb + (OFF_VL + vs1) * 2, Vl + va + vg1);
            asm volatile("cp.async.commit_group;");
            asm volatile("cp.async.wait_group 1;" ::: "memory");
        } else {
            asm volatile("cp.async.wait_group 0;" ::: "memory");
        }
        __syncthreads();

        const bf16* Ks0 = &KV[s][OFF_KH];
        const bf16* Ks1 = &KV[s][OFF_KL];
        const bf16* Vs0 = &KV[s][OFF_VH];
        const bf16* Vs1 = &KV[s][OFF_VL];

        float sreg[8][4];
        #pragma unroll
        for (int nb = 0; nb < 8; nb++)
            sreg[nb][0] = sreg[nb][1] = sreg[nb][2] = sreg[nb][3] = 0.f;

        #pragma unroll
        for (int c = 0; c < 2; c++) {
            #pragma unroll
            for (int jp = 0; jp < 4; jp++) {
                unsigned kh4[4], kl4[4];
                ldsm4(kh4, &Ks0[(jp * 16 + brow) * QSTR + c * 16 + bcol]);
                ldsm4(kl4, &Ks1[(jp * 16 + brow) * QSTR + c * 16 + bcol]);
                mma16816(sreg[2*jp],   qf[0][c], kh4[0], kh4[1]);
                mma16816(sreg[2*jp],   qf[1][c], kh4[0], kh4[1]);
                mma16816(sreg[2*jp],   qf[0][c], kl4[0], kl4[1]);
                mma16816(sreg[2*jp+1], qf[0][c], kh4[2], kh4[3]);
                mma16816(sreg[2*jp+1], qf[1][c], kh4[2], kh4[3]);
                mma16816(sreg[2*jp+1], qf[0][c], kl4[2], kl4[3]);
            }
        }

        float mx0 = sreg[0][0], mx1 = sreg[0][2];
        #pragma unroll
        for (int nb = 0; nb < 8; nb++) {
            mx0 = fmaxf(mx0, fmaxf(sreg[nb][0], sreg[nb][1]));
            mx1 = fmaxf(mx1, fmaxf(sreg[nb][2], sreg[nb][3]));
        }
        mx0 = fmaxf(mx0, __shfl_xor_sync(~0u, mx0, 1));
        mx0 = fmaxf(mx0, __shfl_xor_sync(~0u, mx0, 2));
        mx1 = fmaxf(mx1, __shfl_xor_sync(~0u, mx1, 1));
        mx1 = fmaxf(mx1, __shfl_xor_sync(~0u, mx1, 2));
        float nm0 = fmaxf(m0r, mx0), nm1 = fmaxf(m1r, mx1);
        float sc0 = __expf(m0r - nm0), sc1 = __expf(m1r - nm1);
        m0r = nm0; m1r = nm1;
        float rs0 = 0.f, rs1 = 0.f;
        #pragma unroll
        for (int nb = 0; nb < 8; nb++) {
            sreg[nb][0] = __expf(sreg[nb][0] - nm0);
            sreg[nb][1] = __expf(sreg[nb][1] - nm0);
            sreg[nb][2] = __expf(sreg[nb][2] - nm1);
            sreg[nb][3] = __expf(sreg[nb][3] - nm1);
            rs0 += sreg[nb][0] + sreg[nb][1];
            rs1 += sreg[nb][2] + sreg[nb][3];
        }
        rs0 += __shfl_xor_sync(~0u, rs0, 1);
        rs0 += __shfl_xor_sync(~0u, rs0, 2);
        rs1 += __shfl_xor_sync(~0u, rs1, 1);
        rs1 += __shfl_xor_sync(~0u, rs1, 2);
        l0 = l0 * sc0 + rs0;  l1 = l1 * sc1 + rs1;
        #pragma unroll
        for (int nb = 0; nb < 4; nb++) {
            oacc[nb][0] *= sc0; oacc[nb][1] *= sc0;
            oacc[nb][2] *= sc1; oacc[nb][3] *= sc1;
        }

        #pragma unroll
        for (int c = 0; c < 4; c++) {
            unsigned pah[4], pal[4];
            #pragma unroll
            for (int r4 = 0; r4 < 4; r4++) {
                int nb = 2 * c + (r4 >> 1);
                int pr = (r4 & 1) * 2;
                float x0 = sreg[nb][pr], x1 = sreg[nb][pr + 1];
                bf16 h0 = __float2bfloat16(x0);
                bf16 h1 = __float2bfloat16(x1);
                bf16 e0b = __float2bfloat16(x0 - __bfloat162float(h0));
                bf16 e1b = __float2bfloat16(x1 - __bfloat162float(h1));
                pah[r4] = pack2(h0, h1);
                pal[r4] = pack2(e0b, e1b);
            }
            #pragma unroll
            for (int np = 0; np < 2; np++) {
                unsigned vh4[4], vl4[4];
                ldsm4(vh4, &Vs0[(np * 16 + brow) * VSTR + c * 16 + bcol]);
                ldsm4(vl4, &Vs1[(np * 16 + brow) * VSTR + c * 16 + bcol]);
                mma16816(oacc[2*np],   pah, vh4[0], vh4[1]);
                mma16816(oacc[2*np],   pal, vh4[0], vh4[1]);
                mma16816(oacc[2*np],   pah, vl4[0], vl4[1]);
                mma16816(oacc[2*np+1], pah, vh4[2], vh4[3]);
                mma16816(oacc[2*np+1], pal, vh4[2], vh4[3]);
                mma16816(oacc[2*np+1], pah, vl4[2], vl4[3]);
            }
        }
        __syncthreads();
    }

    float inv0 = 1.f / l0, inv1 = 1.f / l1;
    int r = lane >> 2;
    int qg = q0 + w * 16 + r;
    size_t ob = (size_t)bh * NQ * HD;
    #pragma unroll
    for (int nb = 0; nb < 4; nb++) {
        int d = nb * 8 + (lane & 3) * 2;
        float2 v0 = make_float2(oacc[nb][0] * inv0, oacc[nb][1] * inv0);
        float2 v1 = make_float2(oacc[nb][2] * inv1, oacc[nb][3] * inv1);
        *(float2*)&O[ob + (size_t)qg * HD + d]       = v0;
        *(float2*)&O[ob + (size_t)(qg + 8) * HD + d] = v1;
    }
}

// ============================== launcher ==================================
extern "C" void kernel_launch(void* const* d_in, const int* in_sizes, int n_in,
                              void* d_out, int out_size)
{
    (void)out_size;
    const float *x=0, *y=0, *wxq=0, *bxq=0, *wyq=0, *byq=0,
                *wpx=0, *bpx=0, *wpy=0, *bpy=0;
    for (int i = 0; i < n_in; i++) {
        const float* p = (const float*)d_in[i];
        switch (in_sizes[i]) {
            case 2097152: x = p;   break;
            case 1048576: y = p;   break;
            case 98304:   wxq = p; break;
            case 196608:  wyq = p; break;
            case 32768:   wpx = p; break;
            case 65536:   wpy = p; break;
            case 256:     bpx = p; break;
            case 512:     bpy = p; break;
            case 384:     if (!bxq) bxq = p; else byq = p; break;
            default: break;
        }
    }
    float* out = (float*)d_out;

    qkv_mma2_kernel<<<240, 256>>>(wxq, x, bxq, wyq, y, byq);
    attn_mma_kernel<<<640, 128>>>();
    gemm_proj_kernel<<<768, 256>>>(wpx, bpx, x, wpy, bpy, y, out);
}